// round 1
// baseline (speedup 1.0000x reference)
#include <cuda_runtime.h>
#include <math.h>

// ---------------------------------------------------------------------------
// PCGNN: score precompute + fused select/aggregate/SAGE/out kernel
// Shapes: N_SRC=60000, N_DST=30000, DEG=32, F=128, E=64, C=2, K=16
// ---------------------------------------------------------------------------

#define F_DIM   128
#define E_DIM   64
#define DEG     32
#define KSEL    16
#define NB      8          // nodes per block-iteration
#define THREADS 256

#define N_SRC_MAX 60000
__device__ float g_sig[N_SRC_MAX];   // sigmoid(x[v]·Wd0 + b0) for every source row

// ---- score precompute: one warp per source row --------------------------------
__global__ void score_kernel(const float* __restrict__ x,
                             const float* __restrict__ Wd,   // [128,2] row-major
                             const float* __restrict__ bd,   // [2]
                             float* __restrict__ score_out,  // [n_dst,2]
                             int n_src, int n_dst) {
    int w    = (blockIdx.x * blockDim.x + threadIdx.x) >> 5;
    int lane = threadIdx.x & 31;
    if (w >= n_src) return;
    int f0 = lane * 4;
    float4 xv = *(const float4*)(x + (size_t)w * F_DIM + f0);
    float4 wA = *(const float4*)(Wd + f0 * 2);       // cols for f0, f0+1
    float4 wB = *(const float4*)(Wd + f0 * 2 + 4);   // cols for f0+2, f0+3
    float d0 = xv.x*wA.x + xv.y*wA.z + xv.z*wB.x + xv.w*wB.z;
    float d1 = xv.x*wA.y + xv.y*wA.w + xv.z*wB.y + xv.w*wB.w;
    #pragma unroll
    for (int o = 16; o; o >>= 1) {
        d0 += __shfl_xor_sync(0xffffffffu, d0, o);
        d1 += __shfl_xor_sync(0xffffffffu, d1, o);
    }
    if (lane == 0) {
        float s0 = d0 + bd[0];
        g_sig[w] = 1.0f / (1.0f + expf(-s0));
        if (w < n_dst) {
            score_out[(size_t)w * 2]     = s0;
            score_out[(size_t)w * 2 + 1] = d1 + bd[1];
        }
    }
}

// ---- dynamic SMEM layout (bytes) ----------------------------------------------
#define SM_WB    0        // float2[128*64]  (W_self|W_neigh interleaved)   65536
#define SM_WO    65536    // float2[64]      (W_out rows)                     512
#define SM_BS    66048    // float [64]      (b_sage)                         256
#define SM_XD    66304    // float [128*12]  x_dst transposed [f][node]      6144
#define SM_HN    72448    // float [128*12]  h_neigh transposed [f][node]    6144
#define SM_PART  78592    // float [4*8*64]  partial sums [q][n][e]          8192
#define SM_H     86784    // float [8*64]    relu(h) [n][e]                  2048
#define SM_NBR   88832    // int   [8*32]                                    1024
#define SM_DIFF  89856    // float [8*32]                                    1024
#define SM_SEL   90880    // int   [8*16]    selected neighbor ids            512
#define SM_TOTAL 91392

__global__ __launch_bounds__(THREADS)
void pcgnn_main_kernel(const float* __restrict__ x,
                       const int*   __restrict__ neighbors,
                       const float* __restrict__ W_self,   // [128,64]
                       const float* __restrict__ W_neigh,  // [128,64]
                       const float* __restrict__ b_sage,   // [64]
                       const float* __restrict__ W_out,    // [64,2]
                       const float* __restrict__ b_out,    // [2]
                       float* __restrict__ out_logits,     // [n_dst,2]
                       int n_dst) {
    extern __shared__ char sm[];
    float2* sWb   = (float2*)(sm + SM_WB);
    float2* sWo   = (float2*)(sm + SM_WO);
    float*  sbs   = (float*) (sm + SM_BS);
    float*  sxd   = (float*) (sm + SM_XD);
    float*  shn   = (float*) (sm + SM_HN);
    float*  spart = (float*) (sm + SM_PART);
    float*  sh    = (float*) (sm + SM_H);
    int*    snbr  = (int*)   (sm + SM_NBR);
    float*  sdiff = (float*) (sm + SM_DIFF);
    int*    ssel  = (int*)   (sm + SM_SEL);

    const int tid  = threadIdx.x;
    const int g    = tid >> 5;        // warp / node-group 0..7
    const int lane = tid & 31;

    // Cache weights once per block.
    for (int i = tid; i < F_DIM * E_DIM; i += THREADS) {
        sWb[i] = make_float2(W_self[i], W_neigh[i]);   // i = f*64+e
    }
    if (tid < E_DIM) {
        sWo[tid] = make_float2(W_out[tid * 2], W_out[tid * 2 + 1]);
        sbs[tid] = b_sage[tid];
    }
    const float bo0 = b_out[0], bo1 = b_out[1];
    __syncthreads();

    for (int base = blockIdx.x * NB; base < n_dst; base += gridDim.x * NB) {
        const int node = base + g;
        // ---- Phase A+B: gather scores, rank-select top-16 smallest diffs ----
        if (node < n_dst) {
            int nb = neighbors[(size_t)node * DEG + lane];
            snbr[g * 32 + lane] = nb;
            float t = g_sig[node];
            float d = fabsf(t - g_sig[nb]);
            sdiff[g * 32 + lane] = d;
            __syncwarp();
            int rank = 0;
            float my = d;
            #pragma unroll
            for (int j = 0; j < 32; j++) {
                float dj = sdiff[g * 32 + j];
                rank += (dj < my) || (dj == my && j < lane);
            }
            if (rank < KSEL) ssel[g * KSEL + rank] = nb;
        } else {
            if (lane < KSEL) ssel[g * KSEL + lane] = 0;   // safe dummy
        }
        __syncthreads();

        // ---- Phase C: accumulate selected neighbor means + stage x_dst ----
        {
            const int f = tid & 127;
            const int h = tid >> 7;      // 0 or 1
            #pragma unroll
            for (int np = 0; np < 4; np++) {
                const int gg = np * 2 + h;
                int nd = base + gg;
                if (nd >= n_dst) nd = n_dst - 1;
                float s = 0.f;
                #pragma unroll
                for (int k = 0; k < KSEL; k++) {
                    int idx = ssel[gg * KSEL + k];
                    s += x[(size_t)idx * F_DIM + f];
                }
                shn[f * 12 + gg] = s * 0.0625f;
                sxd[f * 12 + gg] = x[(size_t)nd * F_DIM + f];
            }
        }
        __syncthreads();

        // ---- Phase D: SAGE dual-GEMM, 8 nodes per weight load ----
        {
            const int e = tid & 63;
            const int q = tid >> 6;      // f-quarter 0..3
            float acc[NB];
            #pragma unroll
            for (int n = 0; n < NB; n++) acc[n] = 0.f;
            const int fbase = q * 32;
            #pragma unroll
            for (int ff = 0; ff < 32; ff++) {
                const int f = fbase + ff;
                float2 w = sWb[f * E_DIM + e];
                float4 xa0 = *(const float4*)(sxd + f * 12);
                float4 xa1 = *(const float4*)(sxd + f * 12 + 4);
                float4 hb0 = *(const float4*)(shn + f * 12);
                float4 hb1 = *(const float4*)(shn + f * 12 + 4);
                acc[0] = fmaf(xa0.x, w.x, fmaf(hb0.x, w.y, acc[0]));
                acc[1] = fmaf(xa0.y, w.x, fmaf(hb0.y, w.y, acc[1]));
                acc[2] = fmaf(xa0.z, w.x, fmaf(hb0.z, w.y, acc[2]));
                acc[3] = fmaf(xa0.w, w.x, fmaf(hb0.w, w.y, acc[3]));
                acc[4] = fmaf(xa1.x, w.x, fmaf(hb1.x, w.y, acc[4]));
                acc[5] = fmaf(xa1.y, w.x, fmaf(hb1.y, w.y, acc[5]));
                acc[6] = fmaf(xa1.z, w.x, fmaf(hb1.z, w.y, acc[6]));
                acc[7] = fmaf(xa1.w, w.x, fmaf(hb1.w, w.y, acc[7]));
            }
            #pragma unroll
            for (int n = 0; n < NB; n++)
                spart[(q * NB + n) * E_DIM + e] = acc[n];
        }
        __syncthreads();

        // ---- reduce quarters + bias + relu ----
        for (int p = tid; p < NB * E_DIM; p += THREADS) {
            const int n = p >> 6, e = p & 63;
            float s = spart[(0 * NB + n) * E_DIM + e]
                    + spart[(1 * NB + n) * E_DIM + e]
                    + spart[(2 * NB + n) * E_DIM + e]
                    + spart[(3 * NB + n) * E_DIM + e]
                    + sbs[e];
            sh[n * E_DIM + e] = fmaxf(s, 0.f);
        }
        __syncthreads();

        // ---- Phase E: output projection, warp g -> node base+g ----
        {
            float h0 = sh[g * E_DIM + lane];
            float h1 = sh[g * E_DIM + 32 + lane];
            float2 w0 = sWo[lane];
            float2 w1 = sWo[lane + 32];
            float c0 = h0 * w0.x + h1 * w1.x;
            float c1 = h0 * w0.y + h1 * w1.y;
            #pragma unroll
            for (int o = 16; o; o >>= 1) {
                c0 += __shfl_xor_sync(0xffffffffu, c0, o);
                c1 += __shfl_xor_sync(0xffffffffu, c1, o);
            }
            if (lane == 0 && node < n_dst) {
                out_logits[(size_t)node * 2]     = c0 + bo0;
                out_logits[(size_t)node * 2 + 1] = c1 + bo1;
            }
        }
        __syncthreads();   // smem reused next iteration
    }
}

extern "C" void kernel_launch(void* const* d_in, const int* in_sizes, int n_in,
                              void* d_out, int out_size) {
    const float* x        = (const float*)d_in[0];
    const int*   neighbors= (const int*)  d_in[1];
    const float* W_dist   = (const float*)d_in[2];
    const float* b_dist   = (const float*)d_in[3];
    const float* W_self   = (const float*)d_in[4];
    const float* W_neigh  = (const float*)d_in[5];
    const float* b_sage   = (const float*)d_in[6];
    const float* W_out    = (const float*)d_in[7];
    const float* b_out    = (const float*)d_in[8];

    const int n_src = in_sizes[0] / F_DIM;
    const int n_dst = in_sizes[1] / DEG;

    float* out    = (float*)d_out;
    float* logits = out;                     // [n_dst, 2]
    float* score  = out + (size_t)n_dst * 2; // [n_dst, 2]

    // Kernel 1: per-source score + sigmoid (warp per row, 8 warps/block)
    int blocks1 = (n_src + 7) / 8;
    score_kernel<<<blocks1, 256>>>(x, W_dist, b_dist, score, n_src, n_dst);

    // Kernel 2: fused select + aggregate + SAGE + out-proj
    cudaFuncSetAttribute(pcgnn_main_kernel,
                         cudaFuncAttributeMaxDynamicSharedMemorySize, SM_TOTAL);
    pcgnn_main_kernel<<<296, THREADS, SM_TOTAL>>>(
        x, neighbors, W_self, W_neigh, b_sage, W_out, b_out, logits, n_dst);
}

// round 2
// speedup vs baseline: 1.0464x; 1.0464x over previous
#include <cuda_runtime.h>
#include <math.h>

// ---------------------------------------------------------------------------
// PCGNN: score precompute + fused select/aggregate/SAGE/out kernel
// R2: 512-thread CTAs, NB=16 -> 32 warps/SM (2x occupancy vs R1)
// Shapes: N_SRC=60000, N_DST=30000, DEG=32, F=128, E=64, C=2, K=16
// ---------------------------------------------------------------------------

#define F_DIM   128
#define E_DIM   64
#define DEG     32
#define KSEL    16
#define NB      16         // nodes per block-iteration
#define ST      20         // staging stride (floats): 16B-aligned, 4-way conflicts max
#define THREADS 512

#define N_SRC_MAX 60000
__device__ float g_sig[N_SRC_MAX];   // sigmoid(x[v]·Wd0 + b0) for every source row

// ---- score precompute: one warp per source row --------------------------------
__global__ void score_kernel(const float* __restrict__ x,
                             const float* __restrict__ Wd,   // [128,2] row-major
                             const float* __restrict__ bd,   // [2]
                             float* __restrict__ score_out,  // [n_dst,2]
                             int n_src, int n_dst) {
    int w    = (blockIdx.x * blockDim.x + threadIdx.x) >> 5;
    int lane = threadIdx.x & 31;
    if (w >= n_src) return;
    int f0 = lane * 4;
    float4 xv = *(const float4*)(x + (size_t)w * F_DIM + f0);
    float4 wA = *(const float4*)(Wd + f0 * 2);       // cols for f0, f0+1
    float4 wB = *(const float4*)(Wd + f0 * 2 + 4);   // cols for f0+2, f0+3
    float d0 = xv.x*wA.x + xv.y*wA.z + xv.z*wB.x + xv.w*wB.z;
    float d1 = xv.x*wA.y + xv.y*wA.w + xv.z*wB.y + xv.w*wB.w;
    #pragma unroll
    for (int o = 16; o; o >>= 1) {
        d0 += __shfl_xor_sync(0xffffffffu, d0, o);
        d1 += __shfl_xor_sync(0xffffffffu, d1, o);
    }
    if (lane == 0) {
        float s0 = d0 + bd[0];
        g_sig[w] = 1.0f / (1.0f + expf(-s0));
        if (w < n_dst) {
            score_out[(size_t)w * 2]     = s0;
            score_out[(size_t)w * 2 + 1] = d1 + bd[1];
        }
    }
}

// ---- dynamic SMEM layout (bytes) ----------------------------------------------
#define SM_WB    0          // float2[128*64]  (W_self|W_neigh interleaved)   65536
#define SM_WO    65536      // float2[64]      (W_out rows)                     512
#define SM_BS    66048      // float [64]      (b_sage)                         256
#define SM_XD    66304      // float [128*ST]  x_dst transposed [f][node]     10240
#define SM_HN    76544      // float [128*ST]  h_neigh transposed [f][node]   10240
#define SM_PART  86784      // float [4*16*64] partial sums [q][n][e]         16384
#define SM_H     103168     // float [16*64]   relu(h) [n][e]                  4096
#define SM_NBR   107264     // int   [16*32]                                   2048
#define SM_DIFF  109312     // float [16*32]                                   2048
#define SM_SEL   111360     // int   [16*16]   selected neighbor ids           1024
#define SM_TOTAL 112384

__global__ __launch_bounds__(THREADS)
void pcgnn_main_kernel(const float* __restrict__ x,
                       const int*   __restrict__ neighbors,
                       const float* __restrict__ W_self,   // [128,64]
                       const float* __restrict__ W_neigh,  // [128,64]
                       const float* __restrict__ b_sage,   // [64]
                       const float* __restrict__ W_out,    // [64,2]
                       const float* __restrict__ b_out,    // [2]
                       float* __restrict__ out_logits,     // [n_dst,2]
                       int n_dst) {
    extern __shared__ char sm[];
    float2* sWb   = (float2*)(sm + SM_WB);
    float2* sWo   = (float2*)(sm + SM_WO);
    float*  sbs   = (float*) (sm + SM_BS);
    float*  sxd   = (float*) (sm + SM_XD);
    float*  shn   = (float*) (sm + SM_HN);
    float*  spart = (float*) (sm + SM_PART);
    float*  sh    = (float*) (sm + SM_H);
    int*    snbr  = (int*)   (sm + SM_NBR);
    float*  sdiff = (float*) (sm + SM_DIFF);
    int*    ssel  = (int*)   (sm + SM_SEL);

    const int tid  = threadIdx.x;
    const int g    = tid >> 5;        // warp / node-group 0..15
    const int lane = tid & 31;

    // Cache weights once per block.
    for (int i = tid; i < F_DIM * E_DIM; i += THREADS) {
        sWb[i] = make_float2(W_self[i], W_neigh[i]);   // i = f*64+e
    }
    if (tid < E_DIM) {
        sWo[tid] = make_float2(W_out[tid * 2], W_out[tid * 2 + 1]);
        sbs[tid] = b_sage[tid];
    }
    const float bo0 = b_out[0], bo1 = b_out[1];
    __syncthreads();

    for (int base = blockIdx.x * NB; base < n_dst; base += gridDim.x * NB) {
        const int node = base + g;
        // ---- Phase A+B: gather scores, rank-select top-16 smallest diffs ----
        if (node < n_dst) {
            int nb = neighbors[(size_t)node * DEG + lane];
            snbr[g * 32 + lane] = nb;
            float t = g_sig[node];
            float d = fabsf(t - g_sig[nb]);
            sdiff[g * 32 + lane] = d;
            __syncwarp();
            int rank = 0;
            float my = d;
            #pragma unroll
            for (int j = 0; j < 32; j++) {
                float dj = sdiff[g * 32 + j];
                rank += (dj < my) || (dj == my && j < lane);
            }
            if (rank < KSEL) ssel[g * KSEL + rank] = nb;
        } else {
            if (lane < KSEL) ssel[g * KSEL + lane] = 0;   // safe dummy
        }
        __syncthreads();

        // ---- Phase C: accumulate selected neighbor means + stage x_dst ----
        {
            const int f    = tid & 127;
            const int slot = tid >> 7;      // 0..3 -> 4 nodes each
            #pragma unroll
            for (int np = 0; np < 4; np++) {
                const int gg = np * 4 + slot;
                int nd = base + gg;
                if (nd >= n_dst) nd = n_dst - 1;
                float s = 0.f;
                #pragma unroll
                for (int k = 0; k < KSEL; k++) {
                    int idx = ssel[gg * KSEL + k];
                    s += x[(size_t)idx * F_DIM + f];
                }
                shn[f * ST + gg] = s * 0.0625f;
                sxd[f * ST + gg] = x[(size_t)nd * F_DIM + f];
            }
        }
        __syncthreads();

        // ---- Phase D: SAGE dual-GEMM, quarter-f threads, 8 nodes per thread ----
        {
            const int e  = tid & 63;
            const int q  = (tid >> 6) & 3;   // f-quarter 0..3
            const int h  = tid >> 8;         // node octet 0/1
            const int n0 = h * 8;
            float acc[8];
            #pragma unroll
            for (int n = 0; n < 8; n++) acc[n] = 0.f;
            const int fbase = q * 32;
            #pragma unroll
            for (int ff = 0; ff < 32; ff++) {
                const int f = fbase + ff;
                float2 w = sWb[f * E_DIM + e];
                float4 xa0 = *(const float4*)(sxd + f * ST + n0);
                float4 xa1 = *(const float4*)(sxd + f * ST + n0 + 4);
                float4 hb0 = *(const float4*)(shn + f * ST + n0);
                float4 hb1 = *(const float4*)(shn + f * ST + n0 + 4);
                acc[0] = fmaf(xa0.x, w.x, fmaf(hb0.x, w.y, acc[0]));
                acc[1] = fmaf(xa0.y, w.x, fmaf(hb0.y, w.y, acc[1]));
                acc[2] = fmaf(xa0.z, w.x, fmaf(hb0.z, w.y, acc[2]));
                acc[3] = fmaf(xa0.w, w.x, fmaf(hb0.w, w.y, acc[3]));
                acc[4] = fmaf(xa1.x, w.x, fmaf(hb1.x, w.y, acc[4]));
                acc[5] = fmaf(xa1.y, w.x, fmaf(hb1.y, w.y, acc[5]));
                acc[6] = fmaf(xa1.z, w.x, fmaf(hb1.z, w.y, acc[6]));
                acc[7] = fmaf(xa1.w, w.x, fmaf(hb1.w, w.y, acc[7]));
            }
            #pragma unroll
            for (int n = 0; n < 8; n++)
                spart[(q * NB + n0 + n) * E_DIM + e] = acc[n];
        }
        __syncthreads();

        // ---- reduce quarters + bias + relu (1024 elems, 2 per thread) ----
        #pragma unroll
        for (int r = 0; r < 2; r++) {
            const int p = tid + r * THREADS;
            const int n = p >> 6, e = p & 63;
            float s = spart[(0 * NB + n) * E_DIM + e]
                    + spart[(1 * NB + n) * E_DIM + e]
                    + spart[(2 * NB + n) * E_DIM + e]
                    + spart[(3 * NB + n) * E_DIM + e]
                    + sbs[e];
            sh[n * E_DIM + e] = fmaxf(s, 0.f);
        }
        __syncthreads();

        // ---- Phase E: output projection, warp g -> node base+g ----
        {
            float h0 = sh[g * E_DIM + lane];
            float h1 = sh[g * E_DIM + 32 + lane];
            float2 w0 = sWo[lane];
            float2 w1 = sWo[lane + 32];
            float c0 = h0 * w0.x + h1 * w1.x;
            float c1 = h0 * w0.y + h1 * w1.y;
            #pragma unroll
            for (int o = 16; o; o >>= 1) {
                c0 += __shfl_xor_sync(0xffffffffu, c0, o);
                c1 += __shfl_xor_sync(0xffffffffu, c1, o);
            }
            if (lane == 0 && node < n_dst) {
                out_logits[(size_t)node * 2]     = c0 + bo0;
                out_logits[(size_t)node * 2 + 1] = c1 + bo1;
            }
        }
        __syncthreads();   // smem reused next iteration
    }
}

extern "C" void kernel_launch(void* const* d_in, const int* in_sizes, int n_in,
                              void* d_out, int out_size) {
    const float* x        = (const float*)d_in[0];
    const int*   neighbors= (const int*)  d_in[1];
    const float* W_dist   = (const float*)d_in[2];
    const float* b_dist   = (const float*)d_in[3];
    const float* W_self   = (const float*)d_in[4];
    const float* W_neigh  = (const float*)d_in[5];
    const float* b_sage   = (const float*)d_in[6];
    const float* W_out    = (const float*)d_in[7];
    const float* b_out    = (const float*)d_in[8];

    const int n_src = in_sizes[0] / F_DIM;
    const int n_dst = in_sizes[1] / DEG;

    float* out    = (float*)d_out;
    float* logits = out;                     // [n_dst, 2]
    float* score  = out + (size_t)n_dst * 2; // [n_dst, 2]

    // Kernel 1: per-source score + sigmoid (warp per row, 8 warps/block)
    int blocks1 = (n_src + 7) / 8;
    score_kernel<<<blocks1, 256>>>(x, W_dist, b_dist, score, n_src, n_dst);

    // Kernel 2: fused select + aggregate + SAGE + out-proj
    cudaFuncSetAttribute(pcgnn_main_kernel,
                         cudaFuncAttributeMaxDynamicSharedMemorySize, SM_TOTAL);
    pcgnn_main_kernel<<<296, THREADS, SM_TOTAL>>>(
        x, neighbors, W_self, W_neigh, b_sage, W_out, b_out, logits, n_dst);
}